// round 1
// baseline (speedup 1.0000x reference)
#include <cuda_runtime.h>

// Global accumulator (no cudaMalloc allowed).
__device__ double g_acc;

__global__ void zero_kernel() { g_acc = 0.0; }

__device__ __forceinline__ float skew_elem(float p, float t) {
    float d   = p - t;                 // y_pred - y_true
    float lam = (t - 50.0f) * 0.02f;   // (y-50)/50 — both branches collapse to this
    // gate == 1  <=>  sign(y_true - y_pred)*sign(lam) == 1  <=>  d*lam < 0
    float arg = (d * lam < 0.0f) ? fabsf(lam) : 0.0f;
    return fabsf(d) * __expf(arg);     // __expf(0) == 1 exactly
}

__global__ void skew_reduce_kernel(const float4* __restrict__ yp,
                                   const float4* __restrict__ yt,
                                   int n4) {
    float s = 0.0f;
    int idx    = blockIdx.x * blockDim.x + threadIdx.x;
    int stride = gridDim.x * blockDim.x;
    for (int i = idx; i < n4; i += stride) {
        float4 p = yp[i];
        float4 t = yt[i];
        s += skew_elem(p.x, t.x);
        s += skew_elem(p.y, t.y);
        s += skew_elem(p.z, t.z);
        s += skew_elem(p.w, t.w);
    }
    // warp reduce
    #pragma unroll
    for (int o = 16; o > 0; o >>= 1)
        s += __shfl_xor_sync(0xffffffffu, s, o);

    __shared__ float warp_sums[32];
    int lane = threadIdx.x & 31;
    int wid  = threadIdx.x >> 5;
    if (lane == 0) warp_sums[wid] = s;
    __syncthreads();

    if (wid == 0) {
        int nwarps = blockDim.x >> 5;
        float v = (lane < nwarps) ? warp_sums[lane] : 0.0f;
        #pragma unroll
        for (int o = 16; o > 0; o >>= 1)
            v += __shfl_xor_sync(0xffffffffu, v, o);
        if (lane == 0)
            atomicAdd(&g_acc, (double)v);
    }
}

__global__ void finalize_kernel(float* __restrict__ out, double inv_n) {
    out[0] = (float)(g_acc * inv_n);
}

extern "C" void kernel_launch(void* const* d_in, const int* in_sizes, int n_in,
                              void* d_out, int out_size) {
    const float4* yp = (const float4*)d_in[0];  // y_pred
    const float4* yt = (const float4*)d_in[1];  // y_true
    float* out = (float*)d_out;

    int n  = in_sizes[0];       // 8388608, divisible by 4
    int n4 = n >> 2;

    const int threads = 256;
    int blocks = (n4 + threads * 2 - 1) / (threads * 2);  // ~2 float4 per thread
    if (blocks > 4096) blocks = 4096;
    if (blocks < 1) blocks = 1;

    zero_kernel<<<1, 1>>>();
    skew_reduce_kernel<<<blocks, threads>>>(yp, yt, n4);
    finalize_kernel<<<1, 1>>>(out, 1.0 / (double)n);
}

// round 2
// speedup vs baseline: 1.1600x; 1.1600x over previous
#include <cuda_runtime.h>

// Module-load zero-initialized; the last block of every launch resets them
// back to zero, so every graph replay starts from a clean state.
__device__ double g_acc = 0.0;
__device__ unsigned int g_count = 0u;

__device__ __forceinline__ float skew_elem(float p, float t) {
    float d   = p - t;                 // y_pred - y_true
    float lam = (t - 50.0f) * 0.02f;   // both lamda branches collapse to (t-50)/50
    // gate==1  <=>  sign(y_true - y_pred)*sign(lam) == 1  <=>  d*lam < 0
    float arg = (d * lam < 0.0f) ? fabsf(lam) : 0.0f;
    return fabsf(d) * __expf(arg);     // __expf(0) == 1 exactly
}

__global__ void __launch_bounds__(256)
skew_fused_kernel(const float4* __restrict__ yp,
                  const float4* __restrict__ yt,
                  float* __restrict__ out,
                  int n4, float inv_n) {
    float s = 0.0f;
    int idx    = blockIdx.x * blockDim.x + threadIdx.x;
    int stride = gridDim.x * blockDim.x;
    #pragma unroll 4
    for (int i = idx; i < n4; i += stride) {
        float4 p = yp[i];
        float4 t = yt[i];
        s += skew_elem(p.x, t.x);
        s += skew_elem(p.y, t.y);
        s += skew_elem(p.z, t.z);
        s += skew_elem(p.w, t.w);
    }

    // warp reduce
    #pragma unroll
    for (int o = 16; o > 0; o >>= 1)
        s += __shfl_xor_sync(0xffffffffu, s, o);

    __shared__ float warp_sums[8];
    int lane = threadIdx.x & 31;
    int wid  = threadIdx.x >> 5;
    if (lane == 0) warp_sums[wid] = s;
    __syncthreads();

    if (threadIdx.x == 0) {
        float v = warp_sums[0];
        #pragma unroll
        for (int w = 1; w < 8; w++) v += warp_sums[w];

        atomicAdd(&g_acc, (double)v);
        __threadfence();
        unsigned int done = atomicAdd(&g_count, 1u);
        if (done == gridDim.x - 1) {
            // Last block: finalize and reset state for the next replay.
            double total = g_acc;
            out[0] = (float)total * inv_n;
            g_acc = 0.0;
            g_count = 0u;
        }
    }
}

extern "C" void kernel_launch(void* const* d_in, const int* in_sizes, int n_in,
                              void* d_out, int out_size) {
    const float4* yp = (const float4*)d_in[0];  // y_pred
    const float4* yt = (const float4*)d_in[1];  // y_true
    float* out = (float*)d_out;

    int n  = in_sizes[0];       // 8388608
    int n4 = n >> 2;            // 2097152, exact

    const int threads = 256;
    int blocks = 2048;          // 2048*256*4 = 2097152 exactly (4 iters/thread)
    // Safety for other shapes: ensure full coverage via grid-stride loop anyway.
    if (blocks * threads > n4 && n4 > 0) {
        blocks = (n4 + threads - 1) / threads;
    }

    skew_fused_kernel<<<blocks, threads>>>(yp, yt, out, n4, 1.0f / (float)n);
}